// round 6
// baseline (speedup 1.0000x reference)
#include <cuda_runtime.h>
#include <cstdint>

// Window attention, fully fused, one 8x8 window per CTA.
// All 4 matmul stages (QKV, S=q^T k, AV, proj) use mma.sync m16n8k8 TF32.
// B=8, C=128, H=W=256, WS=8, HEADS=4 (d=32), n=64 tokens/window, 8192 windows.
// R6 = R5 (cp.async smem weight staging, XOR-swizzled, conflict-free LDS
// fragments) + overlap scheduling:
//   - QKV chunk 0 staging issued BEFORE phase-1 x load (latency hidden).
//   - w_proj staging issued between split AV barriers, overlapped with the
//     AV epilogue stores.
// Compute phases bit-identical to R5.

#define C_DIM   128
#define HDIM    256
#define WDIM    256
#define WS      8
#define NTOK    64          // tokens per window
#define HEADS   4
#define DHEAD   32
#define PITCH   68          // smem row pitch (floats): 4*tig+gid bank pattern, conflict-free
#define NTHREADS 256

__device__ __forceinline__ float to_tf32(float x) {
    float r;
    asm("cvt.rna.tf32.f32 %0, %1;" : "=f"(r) : "f"(x));
    return r;
}
__device__ __forceinline__ unsigned f2u(float x) { return __float_as_uint(x); }

__device__ __forceinline__ void mma8(float c[4],
                                     unsigned a0, unsigned a1, unsigned a2, unsigned a3,
                                     unsigned b0, unsigned b1) {
    asm volatile(
        "mma.sync.aligned.m16n8k8.row.col.f32.tf32.tf32.f32 "
        "{%0,%1,%2,%3},{%4,%5,%6,%7},{%8,%9},{%0,%1,%2,%3};"
        : "+f"(c[0]), "+f"(c[1]), "+f"(c[2]), "+f"(c[3])
        : "r"(a0), "r"(a1), "r"(a2), "r"(a3), "r"(b0), "r"(b1));
}

__device__ __forceinline__ void cp_async16(unsigned daddr, const void* src) {
    asm volatile("cp.async.cg.shared.global [%0], [%1], 16;" :: "r"(daddr), "l"(src));
}
__device__ __forceinline__ void cp_async_commit() {
    asm volatile("cp.async.commit_group;");
}
__device__ __forceinline__ void cp_async_wait0() {
    asm volatile("cp.async.wait_group 0;");
}
__device__ __forceinline__ unsigned smem_u32(const void* p) {
    unsigned a;
    asm("{ .reg .u64 t; cvta.to.shared.u64 t, %1; cvt.u32.u64 %0, t; }" : "=r"(a) : "l"(p));
    return a;
}

// Weight staging: rows of 128 floats (512 B = 32 x 16B chunks), chunk-XOR swizzle
// c4' = c4 ^ (row & 7). Fragment LDS bank = 4*(c4^gid)+tig -> conflict-free.
// ws_at(row, col) returns float index into the staging buffer.
__device__ __forceinline__ int ws_at(int row, int col) {
    return row * 128 + ((((col >> 2) ^ (row & 7)) << 2) | (col & 3));
}

// Issue a coalesced float4 staging of 128 weight rows (64 KB) into ws.
__device__ __forceinline__ void stage_issue(unsigned ws_base, const float* wsrc, int tid) {
    const char* src = (const char*)wsrc;
    #pragma unroll
    for (int it = 0; it < 16; it++) {
        int i   = tid + it * NTHREADS;   // 0..4095
        int row = i >> 5;                // 0..127
        int c4  = i & 31;                // 16B chunk in row
        unsigned daddr = ws_base + (unsigned)(row * 512 + ((c4 ^ (row & 7)) << 4));
        cp_async16(daddr, src + row * 512 + (c4 << 4));
    }
    cp_async_commit();
}

// smem layout (floats):
//   qkvs : [384][PITCH]      (q rows 0..127, k rows 128..255, v rows 256..383)
//   Ps4  : [4][64][PITCH]    (attention logits/probs; doubles as 64KB weight staging)
//   xs   : [128][PITCH]      (input window; reused as attention output "outs")
#define SM_QKV   0
#define SM_PS    (384 * PITCH)
#define SM_XS    ((384 + 4 * 64) * PITCH)
#define SMEM_FLOATS ((384 + 4 * 64 + 128) * PITCH)   // 768*68 = 52224 floats = 208896 B

extern "C" __global__ void __launch_bounds__(NTHREADS, 1)
win_attn_kernel(const float* __restrict__ x,
                const float* __restrict__ w_qkv,   // [384][128]
                const float* __restrict__ w_proj,  // [128][128]
                const float* __restrict__ b_proj,  // [128]
                float* __restrict__ out) {
    extern __shared__ float smem[];
    float* qkvs = smem + SM_QKV;
    float* Ps4  = smem + SM_PS;
    float* xs   = smem + SM_XS;   // also "outs" after QKV phase
    float* outs = xs;
    float* ws   = Ps4;            // 64KB weight staging overlays Ps4 when Ps4 is dead
    const unsigned ws_base = smem_u32(ws);

    const int tid  = threadIdx.x;
    const int warp = tid >> 5;
    const int lane = tid & 31;
    const int gid  = lane >> 2;   // group id 0..7
    const int tig  = lane & 3;    // thread in group 0..3

    const int win = blockIdx.x;           // 0..8191
    const int b   = win >> 10;            // batch
    const int hi  = (win >> 5) & 31;      // window row
    const int wi  = win & 31;             // window col
    const int row0 = hi * WS;
    const int col0 = wi * WS;

    const float* xb = x + (size_t)b * C_DIM * HDIM * WDIM;
    float* ob = out + (size_t)b * C_DIM * HDIM * WDIM;

    // ---------- Prefetch QKV weight chunk 0 (ws/Ps4 region is virgin) ----------
    stage_issue(ws_base, w_qkv, tid);

    // ---------- Phase 1: load x window into smem (tf32-rounded, float4) ----------
    // col0 is a multiple of 8 -> 16B-aligned float4 segments of 4 pixels.
    #pragma unroll
    for (int i = tid; i < C_DIM * NTOK / 4; i += NTHREADS) {
        int c  = i >> 4;          // channel
        int t  = (i & 15) * 4;    // token index (multiple of 4)
        const float4 v = *reinterpret_cast<const float4*>(
            xb + (size_t)(c * HDIM + row0 + (t >> 3)) * WDIM + col0 + (t & 7));
        float4 w;
        w.x = to_tf32(v.x); w.y = to_tf32(v.y);
        w.z = to_tf32(v.z); w.w = to_tf32(v.w);
        *reinterpret_cast<float4*>(xs + c * PITCH + t) = w;
    }

    // ---------- Phase 2: QKV GEMM  qkv[384,64] = w_qkv[384,128] @ xs[128,64] ----------
    // 3 chunks of 128 weight rows staged into ws; each warp does one 16-row m-tile/chunk.
    {
        const int rl  = warp * 16 + gid;    // lane's local row within chunk
        for (int ch = 0; ch < 3; ch++) {
            if (ch > 0)   // chunk 0 was issued pre-phase-1
                stage_issue(ws_base, w_qkv + (size_t)ch * 128 * C_DIM, tid);
            cp_async_wait0();
            __syncthreads();   // chunk staged (ch==0: also covers xs stores)

            // --- compute this chunk's 128 output rows ---
            float acc[8][4];
            #pragma unroll
            for (int i = 0; i < 8; i++) { acc[i][0]=0.f; acc[i][1]=0.f; acc[i][2]=0.f; acc[i][3]=0.f; }

            #pragma unroll 4
            for (int k0 = 0; k0 < C_DIM; k0 += 8) {
                unsigned a0 = f2u(to_tf32(ws[ws_at(rl,     k0 + tig    )]));
                unsigned a1 = f2u(to_tf32(ws[ws_at(rl + 8, k0 + tig    )]));
                unsigned a2 = f2u(to_tf32(ws[ws_at(rl,     k0 + tig + 4)]));
                unsigned a3 = f2u(to_tf32(ws[ws_at(rl + 8, k0 + tig + 4)]));
                #pragma unroll
                for (int nt = 0; nt < 8; nt++) {
                    unsigned b0 = f2u(xs[(k0 + tig)     * PITCH + nt * 8 + gid]);
                    unsigned b1 = f2u(xs[(k0 + tig + 4) * PITCH + nt * 8 + gid]);
                    mma8(acc[nt], a0, a1, a2, a3, b0, b1);
                }
            }

            // write qkv rows (tf32-rounded; they become mma operands later)
            const int R = ch * 128 + rl;
            #pragma unroll
            for (int nt = 0; nt < 8; nt++) {
                int c0 = nt * 8 + 2 * tig;
                qkvs[ R      * PITCH + c0    ] = to_tf32(acc[nt][0]);
                qkvs[ R      * PITCH + c0 + 1] = to_tf32(acc[nt][1]);
                qkvs[(R + 8) * PITCH + c0    ] = to_tf32(acc[nt][2]);
                qkvs[(R + 8) * PITCH + c0 + 1] = to_tf32(acc[nt][3]);
            }
            __syncthreads();   // all warps done reading ws before next chunk load
        }
    }
    // qkvs fully written; xs dead (region becomes outs); ws/Ps4 free for S phase.

    // ---------- Phase 3: attention, ALL HEADS batched ----------
    const float scale = 0.1767766952966369f;   // 32^-0.5

    // --- S_h[nq=64, nk=64] = q_h^T k_h for all h.  K = d = 32. ---
    // warp -> m-tile (warp&3), n-tiles [(warp>>2)*4 .. +3]; loop heads inside.
    {
        float sacc[HEADS][4][4];
        #pragma unroll
        for (int h = 0; h < HEADS; h++)
            #pragma unroll
            for (int j = 0; j < 4; j++)
                { sacc[h][j][0]=0.f; sacc[h][j][1]=0.f; sacc[h][j][2]=0.f; sacc[h][j][3]=0.f; }

        const int mt  = warp & 3;
        const int ntb = (warp >> 2) * 4;
        // hoisted base pointers (tig row offset folded in)
        const float* qbase = qkvs + tig * PITCH + mt * 16 + gid;
        const float* kbase = qkvs + 128 * PITCH + tig * PITCH + gid;
        #pragma unroll
        for (int k0 = 0; k0 < DHEAD; k0 += 8) {
            #pragma unroll
            for (int h = 0; h < HEADS; h++) {
                const float* qp = qbase + (h * DHEAD + k0) * PITCH;
                const float* kp = kbase + (h * DHEAD + k0) * PITCH;
                // A[nq][kd] = q[kd][nq]  (transposed read)
                unsigned a0 = f2u(qp[0]);
                unsigned a1 = f2u(qp[8]);
                unsigned a2 = f2u(qp[4 * PITCH]);
                unsigned a3 = f2u(qp[4 * PITCH + 8]);
                #pragma unroll
                for (int j = 0; j < 4; j++) {
                    int nc = (ntb + j) * 8;
                    unsigned b0 = f2u(kp[nc]);
                    unsigned b1 = f2u(kp[4 * PITCH + nc]);
                    mma8(sacc[h][j], a0, a1, a2, a3, b0, b1);
                }
            }
        }
        #pragma unroll
        for (int h = 0; h < HEADS; h++) {
            float* Ps = Ps4 + h * NTOK * PITCH;
            #pragma unroll
            for (int j = 0; j < 4; j++) {
                int nq = mt * 16 + gid;
                int cc = (ntb + j) * 8 + 2 * tig;
                Ps[ nq      * PITCH + cc    ] = sacc[h][j][0] * scale;
                Ps[ nq      * PITCH + cc + 1] = sacc[h][j][1] * scale;
                Ps[(nq + 8) * PITCH + cc    ] = sacc[h][j][2] * scale;
                Ps[(nq + 8) * PITCH + cc + 1] = sacc[h][j][3] * scale;
            }
        }
    }
    __syncthreads();

    // --- softmax over keys, all heads. 4 threads per row; each thread does 4 rows ---
    {
        const int row = tid >> 2;
        const int q4  = tid & 3;
        #pragma unroll
        for (int h = 0; h < HEADS; h++) {
            float* Ps = Ps4 + h * NTOK * PITCH;
            float r[16];
            float m = -1e30f;
            #pragma unroll
            for (int i = 0; i < 16; i++) {
                r[i] = Ps[row * PITCH + q4 + 4 * i];
                m = fmaxf(m, r[i]);
            }
            m = fmaxf(m, __shfl_xor_sync(0xffffffffu, m, 1));
            m = fmaxf(m, __shfl_xor_sync(0xffffffffu, m, 2));
            float s = 0.f;
            #pragma unroll
            for (int i = 0; i < 16; i++) { r[i] = __expf(r[i] - m); s += r[i]; }
            s += __shfl_xor_sync(0xffffffffu, s, 1);
            s += __shfl_xor_sync(0xffffffffu, s, 2);
            const float inv = 1.f / s;
            #pragma unroll
            for (int i = 0; i < 16; i++)
                Ps[row * PITCH + q4 + 4 * i] = to_tf32(r[i] * inv);
        }
    }
    __syncthreads();

    // --- AV: out_h[d=32, nq=64] = v_h[32,64] @ P_h^T for all h.  K = nk = 64 ---
    // warp -> m-tile (warp&1), n-tiles [(warp>>1)*2 .. +1]; loop heads inside.
    {
        float vacc[HEADS][2][4];
        #pragma unroll
        for (int h = 0; h < HEADS; h++)
            #pragma unroll
            for (int j = 0; j < 2; j++)
                { vacc[h][j][0]=0.f; vacc[h][j][1]=0.f; vacc[h][j][2]=0.f; vacc[h][j][3]=0.f; }

        const int mtv  = warp & 1;
        const int ntb2 = (warp >> 1) * 2;
        #pragma unroll
        for (int k0 = 0; k0 < NTOK; k0 += 8) {
            #pragma unroll
            for (int h = 0; h < HEADS; h++) {
                const float* vs = qkvs + (256 + h * DHEAD) * PITCH;
                const float* Ps = Ps4 + h * NTOK * PITCH;
                unsigned a0 = f2u(vs[(mtv * 16 + gid)     * PITCH + k0 + tig    ]);
                unsigned a1 = f2u(vs[(mtv * 16 + gid + 8) * PITCH + k0 + tig    ]);
                unsigned a2 = f2u(vs[(mtv * 16 + gid)     * PITCH + k0 + tig + 4]);
                unsigned a3 = f2u(vs[(mtv * 16 + gid + 8) * PITCH + k0 + tig + 4]);
                #pragma unroll
                for (int j = 0; j < 2; j++) {
                    int nt = ntb2 + j;
                    unsigned b0 = f2u(Ps[(nt * 8 + gid) * PITCH + k0 + tig    ]);
                    unsigned b1 = f2u(Ps[(nt * 8 + gid) * PITCH + k0 + tig + 4]);
                    mma8(vacc[h][j], a0, a1, a2, a3, b0, b1);
                }
            }
        }
        __syncthreads();   // sync#1: all Ps reads done everywhere -> Ps4/ws dead

        // stage w_proj NOW; its latency overlaps the outs stores below
        stage_issue(ws_base, w_proj, tid);

        #pragma unroll
        for (int h = 0; h < HEADS; h++) {
            #pragma unroll
            for (int j = 0; j < 2; j++) {
                int d  = mtv * 16 + gid;
                int cc = (ntb2 + j) * 8 + 2 * tig;
                outs[(h * DHEAD + d)     * PITCH + cc    ] = to_tf32(vacc[h][j][0]);
                outs[(h * DHEAD + d)     * PITCH + cc + 1] = to_tf32(vacc[h][j][1]);
                outs[(h * DHEAD + d + 8) * PITCH + cc    ] = to_tf32(vacc[h][j][2]);
                outs[(h * DHEAD + d + 8) * PITCH + cc + 1] = to_tf32(vacc[h][j][3]);
            }
        }
    }

    // ---------- Phase 4: proj  out[128,64] = w_proj[128,128] @ outs + b_proj ----------
    {
        const int r = warp * 16 + gid;   // one m-tile of 16 rows per warp (global row)
        const float bias0 = b_proj[r];
        const float bias8 = b_proj[r + 8];
        cp_async_wait0();
        __syncthreads();   // sync#2: outs written + w_proj staged

        float pacc[8][4];
        #pragma unroll
        for (int i = 0; i < 8; i++) { pacc[i][0]=0.f; pacc[i][1]=0.f; pacc[i][2]=0.f; pacc[i][3]=0.f; }

        #pragma unroll 4
        for (int k0 = 0; k0 < C_DIM; k0 += 8) {
            unsigned a0 = f2u(to_tf32(ws[ws_at(r,     k0 + tig    )]));
            unsigned a1 = f2u(to_tf32(ws[ws_at(r + 8, k0 + tig    )]));
            unsigned a2 = f2u(to_tf32(ws[ws_at(r,     k0 + tig + 4)]));
            unsigned a3 = f2u(to_tf32(ws[ws_at(r + 8, k0 + tig + 4)]));
            #pragma unroll
            for (int nt = 0; nt < 8; nt++) {
                unsigned b0 = f2u(outs[(k0 + tig)     * PITCH + nt * 8 + gid]);
                unsigned b1 = f2u(outs[(k0 + tig + 4) * PITCH + nt * 8 + gid]);
                mma8(pacc[nt], a0, a1, a2, a3, b0, b1);
            }
        }
        #pragma unroll
        for (int nt = 0; nt < 8; nt++) {
            // token t = nt*8 + 2*tig (+1):  pixel row = row0+nt, col = col0 + 2*tig (+1)
            float2 v0; v0.x = pacc[nt][0] + bias0; v0.y = pacc[nt][1] + bias0;
            float2 v8; v8.x = pacc[nt][2] + bias8; v8.y = pacc[nt][3] + bias8;
            *reinterpret_cast<float2*>(
                ob + (size_t)( r      * HDIM + row0 + nt) * WDIM + col0 + 2 * tig) = v0;
            *reinterpret_cast<float2*>(
                ob + (size_t)((r + 8) * HDIM + row0 + nt) * WDIM + col0 + 2 * tig) = v8;
        }
    }
}

extern "C" void kernel_launch(void* const* d_in, const int* in_sizes, int n_in,
                              void* d_out, int out_size) {
    const float* x      = (const float*)d_in[0];
    const float* w_qkv  = (const float*)d_in[1];
    const float* w_proj = (const float*)d_in[2];
    const float* b_proj = (const float*)d_in[3];
    float* out = (float*)d_out;

    const int smem_bytes = SMEM_FLOATS * (int)sizeof(float);   // 208,896 B
    cudaFuncSetAttribute(win_attn_kernel,
                         cudaFuncAttributeMaxDynamicSharedMemorySize, smem_bytes);

    win_attn_kernel<<<8192, NTHREADS, smem_bytes>>>(x, w_qkv, w_proj, b_proj, out);
}

// round 13
// speedup vs baseline: 2.2678x; 2.2678x over previous
#include <cuda_runtime.h>
#include <cuda_fp16.h>
#include <cstdint>

// Window attention, fully fused, one 8x8 window per CTA. R13 == R12/R11/R10
// (6x hand-verified; broker has never run it): fp16 mma.m16n8k16 (f32 accum),
// ldmatrix operand fetch (odd-16B pitches, conflict-free), weights
// fp16-prepped and cp.async-staged THROUGH THE P REGION in chunks ->
// smem 110.6KB -> 2 CTAs/SM.
// R6 measured: L1=74.5% (crossbar wall -> fp16+ldsm), occ=12.4% (-> 2 CTA/SM).
// B=8, C=128, H=W=256, WS=8, HEADS=4 (d=32), n=64 tok/window, 8192 windows.

#define C_DIM   128
#define HDIM    256
#define WDIM    256
#define WS      8
#define NTOK    64
#define HEADS   4
#define NTHREADS 256

#define PQ  72     // pitch (halves) for xs/qkv/P/outs: 144B = 9*16B (odd -> ldmatrix CF)
#define PW  136    // pitch (halves) for weight staging: 272B = 17*16B (odd)

// smem layout in halves:
#define SM_XS   0                        // xs[c][t]: 128 x PQ   (later outs[d][t])
#define SM_QKV  (128 * PQ)               // qkv[o][t]: 384 x PQ
#define SM_P    (SM_QKV + 384 * PQ)      // P[h][tq][tk]: 4 x 64 x PQ  (= 18432 halves)
                                         // doubles as weight staging: 128 x PW = 17408 ✓
#define SMEM_HALVES (SM_P + 4 * 64 * PQ) // 55,296 halves = 110,592 B  -> 2 CTAs/SM

__device__ __half g_wq_h[384 * 128];
__device__ __half g_wp_h[128 * 128];

__global__ void prep_weights(const float* __restrict__ wq, const float* __restrict__ wp) {
    int i = blockIdx.x * blockDim.x + threadIdx.x;
    if (i < 384 * 128) g_wq_h[i] = __float2half_rn(wq[i]);
    if (i < 128 * 128) g_wp_h[i] = __float2half_rn(wp[i]);
}

__device__ __forceinline__ void mma16(float c[4], unsigned a0, unsigned a1, unsigned a2,
                                      unsigned a3, unsigned b0, unsigned b1) {
    asm volatile(
        "mma.sync.aligned.m16n8k16.row.col.f32.f16.f16.f32 "
        "{%0,%1,%2,%3},{%4,%5,%6,%7},{%8,%9},{%0,%1,%2,%3};"
        : "+f"(c[0]), "+f"(c[1]), "+f"(c[2]), "+f"(c[3])
        : "r"(a0), "r"(a1), "r"(a2), "r"(a3), "r"(b0), "r"(b1));
}

__device__ __forceinline__ void ldsm4(unsigned& r0, unsigned& r1, unsigned& r2, unsigned& r3,
                                      unsigned a) {
    asm volatile("ldmatrix.sync.aligned.m8n8.x4.shared.b16 {%0,%1,%2,%3}, [%4];"
                 : "=r"(r0), "=r"(r1), "=r"(r2), "=r"(r3) : "r"(a));
}
__device__ __forceinline__ void ldsm4t(unsigned& r0, unsigned& r1, unsigned& r2, unsigned& r3,
                                       unsigned a) {
    asm volatile("ldmatrix.sync.aligned.m8n8.x4.trans.shared.b16 {%0,%1,%2,%3}, [%4];"
                 : "=r"(r0), "=r"(r1), "=r"(r2), "=r"(r3) : "r"(a));
}

__device__ __forceinline__ void cp_async16(unsigned daddr, const void* src) {
    asm volatile("cp.async.cg.shared.global [%0], [%1], 16;" :: "r"(daddr), "l"(src));
}
__device__ __forceinline__ void cp_async_commit() { asm volatile("cp.async.commit_group;"); }
__device__ __forceinline__ void cp_async_wait0()  { asm volatile("cp.async.wait_group 0;"); }
__device__ __forceinline__ unsigned smem_u32(const void* p) {
    unsigned a;
    asm("{ .reg .u64 t; cvta.to.shared.u64 t, %1; cvt.u32.u64 %0, t; }" : "=r"(a) : "l"(p));
    return a;
}

// ldmatrix address helpers. lane -> (q = lane>>3 matrix id, r = lane&7 row).
// A fragment (16x16) regs: a0=(gid,2tig) a1=(gid+8) a2=(gid,2tig+8) a3=(gid+8,2tig+8)
// B fragment (16x8)  regs: b0=(2tig,gid) b1=(2tig+8,gid)
// A-direct from [m][k]; A-trans from [k][m]; B-direct from [n][k]; B-trans from [k][n].
__device__ __forceinline__ unsigned adr_Ad(unsigned base, int q, int r, int m0, int k0, int P) {
    return base + 2u * (unsigned)((m0 + (q & 1) * 8 + r) * P + k0 + (q >> 1) * 8);
}
__device__ __forceinline__ unsigned adr_At(unsigned base, int q, int r, int m0, int k0, int P) {
    return base + 2u * (unsigned)((k0 + (q >> 1) * 8 + r) * P + m0 + (q & 1) * 8);
}
__device__ __forceinline__ unsigned adr_Bd(unsigned base, int q, int r, int n0, int k0, int P) {
    return base + 2u * (unsigned)((n0 + (q >> 1) * 8 + r) * P + k0 + (q & 1) * 8);
}
__device__ __forceinline__ unsigned adr_Bt(unsigned base, int q, int r, int n0, int k0, int P) {
    return base + 2u * (unsigned)((k0 + (q & 1) * 8 + r) * P + n0 + (q >> 1) * 8);
}

// Stage 128 fp16 weight rows (256B each) into the staging region at pitch PW.
__device__ __forceinline__ void stage128(unsigned wb_base, const __half* wsrc, int tid) {
    const char* src = (const char*)wsrc;
    #pragma unroll
    for (int it = 0; it < 8; it++) {
        int i   = tid + it * NTHREADS;   // 0..2047
        int row = i >> 4;                // 0..127
        int c16 = i & 15;
        cp_async16(wb_base + (unsigned)(row * (PW * 2) + c16 * 16),
                   src + row * 256 + c16 * 16);
    }
    cp_async_commit();
}

extern "C" __global__ void __launch_bounds__(NTHREADS, 2)
win_attn_kernel(const float* __restrict__ x,
                const float* __restrict__ w_qkv,   // unused (prep'd)
                const float* __restrict__ w_proj,  // unused (prep'd)
                const float* __restrict__ b_proj,
                float* __restrict__ out) {
    extern __shared__ __half smh[];
    __half* xsp  = smh + SM_XS;    // xs[c][t], later outs[d][t]
    __half* qkvp = smh + SM_QKV;   // qkv[o][t]
    __half* Pp   = smh + SM_P;     // P[h][tq][tk]  / weight staging
    const unsigned xs_base = smem_u32(xsp);
    const unsigned qk_base = smem_u32(qkvp);
    const unsigned P_base  = smem_u32(Pp);
    const unsigned wb_base = P_base;          // staging overlays P

    const int tid  = threadIdx.x;
    const int warp = tid >> 5;
    const int lane = tid & 31;
    const int gid  = lane >> 2;
    const int tig  = lane & 3;
    const int q    = lane >> 3;    // ldmatrix matrix id
    const int r    = lane & 7;     // ldmatrix row id

    const int win = blockIdx.x;
    const int b   = win >> 10;
    const int hi  = (win >> 5) & 31;
    const int wi  = win & 31;
    const int row0 = hi * WS;
    const int col0 = wi * WS;

    const float* xb = x + (size_t)b * C_DIM * HDIM * WDIM;
    float* ob = out + (size_t)b * C_DIM * HDIM * WDIM;

    // ---------- pre-issue w_qkv chunk 0 (staging region is virgin) ----------
    stage128(wb_base, g_wq_h, tid);

    // ---------- Phase 1: x window -> xs[c][t] fp16 ----------
    // One thread = one 8-token row segment: 2 float4 LDG -> one 16B STS.
    // 16B-chunk index (9c + t/8): (c+u) mod 8 all distinct -> conflict-free.
    #pragma unroll
    for (int i = tid; i < C_DIM * NTOK / 8; i += NTHREADS) {
        int c = i >> 3;
        int t = (i & 7) * 8;
        const float* src = xb + (size_t)(c * HDIM + row0 + (t >> 3)) * WDIM + col0;
        const float4 v0 = *reinterpret_cast<const float4*>(src);
        const float4 v1 = *reinterpret_cast<const float4*>(src + 4);
        __half2 h[4];
        h[0] = __floats2half2_rn(v0.x, v0.y);
        h[1] = __floats2half2_rn(v0.z, v0.w);
        h[2] = __floats2half2_rn(v1.x, v1.y);
        h[3] = __floats2half2_rn(v1.z, v1.w);
        *reinterpret_cast<float4*>(xsp + c * PQ + t) = *reinterpret_cast<float4*>(h);
    }

    // ---------- Phase 2: QKV  D[o=384][t=64] = w[o][c] * xs[c][t] ----------
    // 3 chunks of 128 rows staged through P; warp = 1 m-tile/chunk, 8 n-tiles.
    for (int ch = 0; ch < 3; ch++) {
        cp_async_wait0();
        __syncthreads();   // chunk ch staged (ch==0 also covers xs stores)

        float acc[8][4];
        #pragma unroll
        for (int i = 0; i < 8; i++) { acc[i][0]=0.f; acc[i][1]=0.f; acc[i][2]=0.f; acc[i][3]=0.f; }

        #pragma unroll
        for (int ks = 0; ks < 8; ks++) {
            const int k0 = ks * 16;
            unsigned a0, a1, a2, a3;
            ldsm4(a0, a1, a2, a3, adr_Ad(wb_base, q, r, warp * 16, k0, PW));
            unsigned B[4][4];
            #pragma unroll
            for (int np = 0; np < 4; np++)
                ldsm4t(B[np][0], B[np][1], B[np][2], B[np][3],
                       adr_Bt(xs_base, q, r, np * 16, k0, PQ));
            #pragma unroll
            for (int nt = 0; nt < 8; nt++)
                mma16(acc[nt], a0, a1, a2, a3,
                      B[nt >> 1][(nt & 1) * 2], B[nt >> 1][(nt & 1) * 2 + 1]);
        }
        const int o = ch * 128 + warp * 16 + gid;
        #pragma unroll
        for (int nt = 0; nt < 8; nt++) {
            const int t = nt * 8 + 2 * tig;
            *reinterpret_cast<__half2*>(qkvp + o * PQ + t) =
                __floats2half2_rn(acc[nt][0], acc[nt][1]);
            *reinterpret_cast<__half2*>(qkvp + (o + 8) * PQ + t) =
                __floats2half2_rn(acc[nt][2], acc[nt][3]);
        }
        __syncthreads();   // all reads of chunk ch done
        if (ch < 2)
            stage128(wb_base, g_wq_h + (size_t)(ch + 1) * 128 * C_DIM, tid);
    }
    // qkv ready; staging region (P) free until phase 3a writes.

    // ---------- Phase 3a: S[h][nq][nk] = q^T k, k-dim d = 32 (2 steps) ----------
    // warp: mt = warp&3 (nq tile), nk range (warp>>2)*32 .. +31.
    const float scale = 0.1767766952966369f;
    {
        const int mt = warp & 3;
        const int nh = warp >> 2;
        float sacc[HEADS][4][4];
        #pragma unroll
        for (int h = 0; h < HEADS; h++)
            #pragma unroll
            for (int j = 0; j < 4; j++)
                { sacc[h][j][0]=0.f; sacc[h][j][1]=0.f; sacc[h][j][2]=0.f; sacc[h][j][3]=0.f; }

        #pragma unroll
        for (int kd = 0; kd < 32; kd += 16) {
            #pragma unroll
            for (int h = 0; h < HEADS; h++) {
                const int k0 = h * 32 + kd;
                unsigned a0, a1, a2, a3;
                ldsm4t(a0, a1, a2, a3, adr_At(qk_base, q, r, mt * 16, k0, PQ));
                unsigned B[2][4];
                #pragma unroll
                for (int g = 0; g < 2; g++)
                    ldsm4t(B[g][0], B[g][1], B[g][2], B[g][3],
                           adr_Bt(qk_base, q, r, nh * 32 + g * 16, 128 + k0, PQ));
                #pragma unroll
                for (int nt = 0; nt < 4; nt++)
                    mma16(sacc[h][nt], a0, a1, a2, a3,
                          B[nt >> 1][(nt & 1) * 2], B[nt >> 1][(nt & 1) * 2 + 1]);
            }
        }
        #pragma unroll
        for (int h = 0; h < HEADS; h++) {
            __half* Ph = Pp + h * NTOK * PQ;
            const int nq = mt * 16 + gid;
            #pragma unroll
            for (int nt = 0; nt < 4; nt++) {
                const int nk = nh * 32 + nt * 8 + 2 * tig;
                *reinterpret_cast<__half2*>(Ph + nq * PQ + nk) =
                    __floats2half2_rn(sacc[h][nt][0] * scale, sacc[h][nt][1] * scale);
                *reinterpret_cast<__half2*>(Ph + (nq + 8) * PQ + nk) =
                    __floats2half2_rn(sacc[h][nt][2] * scale, sacc[h][nt][3] * scale);
            }
        }
    }
    __syncthreads();

    // ---------- Phase 3b: softmax over nk (rows of P) ----------
    {
        const int row = tid >> 2;
        const int q4  = tid & 3;
        #pragma unroll
        for (int h = 0; h < HEADS; h++) {
            __half2* Pr = reinterpret_cast<__half2*>(Pp + h * NTOK * PQ + row * PQ);
            float rx[8], ry[8];
            float m = -1e30f;
            #pragma unroll
            for (int j = 0; j < 8; j++) {
                float2 f = __half22float2(Pr[q4 + 4 * j]);
                rx[j] = f.x; ry[j] = f.y;
                m = fmaxf(m, fmaxf(f.x, f.y));
            }
            m = fmaxf(m, __shfl_xor_sync(0xffffffffu, m, 1));
            m = fmaxf(m, __shfl_xor_sync(0xffffffffu, m, 2));
            float s = 0.f;
            #pragma unroll
            for (int j = 0; j < 8; j++) {
                rx[j] = __expf(rx[j] - m);
                ry[j] = __expf(ry[j] - m);
                s += rx[j] + ry[j];
            }
            s += __shfl_xor_sync(0xffffffffu, s, 1);
            s += __shfl_xor_sync(0xffffffffu, s, 2);
            const float inv = 1.f / s;
            #pragma unroll
            for (int j = 0; j < 8; j++)
                Pr[q4 + 4 * j] = __floats2half2_rn(rx[j] * inv, ry[j] * inv);
        }
    }
    __syncthreads();

    // ---------- Phase 3c: AV  D[d][tq] = v[d][tk] * P^T,  k = tk = 64 (4 steps) ----------
    // warp: dt = warp&1 (d tile within head), tq tiles at n0 = (warp>>1)*16.
    float bias0, bias8;
    {
        const int dt = warp & 1;
        const int n0 = (warp >> 1) * 16;
        float vacc[HEADS][2][4];
        #pragma unroll
        for (int h = 0; h < HEADS; h++)
            #pragma unroll
            for (int j = 0; j < 2; j++)
                { vacc[h][j][0]=0.f; vacc[h][j][1]=0.f; vacc[h][j][2]=0.f; vacc[h][j][3]=0.f; }

        #pragma unroll
        for (int ks = 0; ks < 4; ks++) {
            const int tk0 = ks * 16;
            #pragma unroll
            for (int h = 0; h < HEADS; h++) {
                unsigned a0, a1, a2, a3;
                ldsm4(a0, a1, a2, a3,
                      adr_Ad(qk_base, q, r, 256 + h * 32 + dt * 16, tk0, PQ));
                unsigned b0, b1, b2, b3;
                ldsm4(b0, b1, b2, b3,
                      adr_Bd(P_base + (unsigned)(h * NTOK * PQ * 2), q, r, n0, tk0, PQ));
                mma16(vacc[h][0], a0, a1, a2, a3, b0, b1);
                mma16(vacc[h][1], a0, a1, a2, a3, b2, b3);
            }
        }
        __syncthreads();   // all P reads done -> staging region free

        // stage w_proj; latency overlaps the outs stores below
        stage128(wb_base, g_wp_h, tid);
        // hoisted bias loads: gmem latency hides behind the epilogue stores
        bias0 = b_proj[warp * 16 + gid];
        bias8 = b_proj[warp * 16 + gid + 8];

        // outs[d][t] overlays xs (dead)
        #pragma unroll
        for (int h = 0; h < HEADS; h++) {
            const int d = h * 32 + dt * 16 + gid;
            #pragma unroll
            for (int j = 0; j < 2; j++) {
                const int t = n0 + j * 8 + 2 * tig;
                *reinterpret_cast<__half2*>(xsp + d * PQ + t) =
                    __floats2half2_rn(vacc[h][j][0], vacc[h][j][1]);
                *reinterpret_cast<__half2*>(xsp + (d + 8) * PQ + t) =
                    __floats2half2_rn(vacc[h][j][2], vacc[h][j][3]);
            }
        }
    }
    cp_async_wait0();
    __syncthreads();   // outs written + w_proj staged

    // ---------- Phase 4: proj  D[o=128][t=64] = w_proj[o][c] * outs[c][t] + bias ----------
    // warp: 1 m-tile (o = warp*16), all 8 n-tiles; k = 8 steps.
    {
        const int o0 = warp * 16;
        const int ro = o0 + gid;

        float pacc[8][4];
        #pragma unroll
        for (int i = 0; i < 8; i++) { pacc[i][0]=0.f; pacc[i][1]=0.f; pacc[i][2]=0.f; pacc[i][3]=0.f; }

        #pragma unroll
        for (int ks = 0; ks < 8; ks++) {
            const int k0 = ks * 16;
            unsigned a0, a1, a2, a3;
            ldsm4(a0, a1, a2, a3, adr_Ad(wb_base, q, r, o0, k0, PW));
            unsigned B[4][4];
            #pragma unroll
            for (int np = 0; np < 4; np++)
                ldsm4t(B[np][0], B[np][1], B[np][2], B[np][3],
                       adr_Bt(xs_base, q, r, np * 16, k0, PQ));
            #pragma unroll
            for (int nt = 0; nt < 8; nt++)
                mma16(pacc[nt], a0, a1, a2, a3,
                      B[nt >> 1][(nt & 1) * 2], B[nt >> 1][(nt & 1) * 2 + 1]);
        }
        #pragma unroll
        for (int nt = 0; nt < 8; nt++) {
            // token t = nt*8 + 2tig (+1): pixel row = row0+nt, col = col0 + 2tig (+1)
            float2 v0; v0.x = pacc[nt][0] + bias0; v0.y = pacc[nt][1] + bias0;
            float2 v8; v8.x = pacc[nt][2] + bias8; v8.y = pacc[nt][3] + bias8;
            *reinterpret_cast<float2*>(
                ob + (size_t)( ro      * HDIM + row0 + nt) * WDIM + col0 + 2 * tig) = v0;
            *reinterpret_cast<float2*>(
                ob + (size_t)((ro + 8) * HDIM + row0 + nt) * WDIM + col0 + 2 * tig) = v8;
        }
    }
}

extern "C" void kernel_launch(void* const* d_in, const int* in_sizes, int n_in,
                              void* d_out, int out_size) {
    const float* x      = (const float*)d_in[0];
    const float* w_qkv  = (const float*)d_in[1];
    const float* w_proj = (const float*)d_in[2];
    const float* b_proj = (const float*)d_in[3];
    float* out = (float*)d_out;

    prep_weights<<<192, 256>>>(w_qkv, w_proj);

    const int smem_bytes = SMEM_HALVES * 2;   // 110,592 B -> 2 CTAs/SM
    cudaFuncSetAttribute(win_attn_kernel,
                         cudaFuncAttributeMaxDynamicSharedMemorySize, smem_bytes);
    win_attn_kernel<<<8192, NTHREADS, smem_bytes>>>(x, w_qkv, w_proj, b_proj, out);
}